// round 5
// baseline (speedup 1.0000x reference)
#include <cuda_runtime.h>

#define KN 40
#define FN 32
#define VPW 4                // vertices per warp
#define WPB 8                // warps per block
#define WSH 800              // floats per warp: rec4 640 + fb 160 (staging reuses: 392+384=776)
#define SSTR 392             // staging stride (mult of 4 -> float4 aligned)

__device__ float4 g_coords4[131072];   // padded coords scratch (V <= 131072)

__device__ __forceinline__ unsigned long long pack2(float lo, float hi) {
    unsigned long long r;
    asm("mov.b64 %0, {%1,%2};" : "=l"(r) : "f"(lo), "f"(hi));
    return r;
}
__device__ __forceinline__ void unpack2(unsigned long long v, float& lo, float& hi) {
    asm("mov.b64 {%0,%1}, %2;" : "=f"(lo), "=f"(hi) : "l"(v));
}
__device__ __forceinline__ unsigned long long ffma2(unsigned long long a,
                                                    unsigned long long b,
                                                    unsigned long long c) {
    unsigned long long d;
    asm("fma.rn.f32x2 %0, %1, %2, %3;" : "=l"(d) : "l"(a), "l"(b), "l"(c));
    return d;
}

__global__ void pad_coords_kernel(const float* __restrict__ c, int V) {
    int i = blockIdx.x * blockDim.x + threadIdx.x;
    if (i < V) {
        g_coords4[i] = make_float4(c[3*i], c[3*i+1], c[3*i+2], 0.f);
    }
}

__global__ __launch_bounds__(WPB * 32)
void nbcov_kernel(const float* __restrict__ distsq,
                  const float* __restrict__ feats,
                  const int* __restrict__ nidx,
                  float* __restrict__ out, int V)
{
    __shared__ float smem[WPB * WSH];
    const int warp = threadIdx.x >> 5;
    const int lane = threadIdx.x & 31;
    const int vbase = (blockIdx.x * WPB + warp) * VPW;
    float* ws = smem + warp * WSH;

    float4* rec4 = (float4*)ws;          // [vloc*40 + k] : (x,y,z,w)
    int*    fbA  = (int*)(ws + 640);     // [vloc*40 + k] : ia*FN

    // ---------- prep: 160 (vertex,k) tasks; tiny 5-float records ----------
    #pragma unroll
    for (int t = 0; t < 5; ++t) {
        const int id = t * 32 + lane;          // 0..159, lexicographic (vloc,k)
        const int v = vbase + id / KN;
        float w = 0.f;
        int ia = 0;
        float4 c4 = make_float4(0.f, 0.f, 0.f, 0.f);
        if (v < V) {
            const int ko = vbase * KN + id;    // contiguous loads
            int t_ia = nidx[ko];
            float d = distsq[ko];
            if (t_ia >= 0) { w = __expf(-10.0f * d); ia = t_ia; }
            c4 = g_coords4[ia];                // single LDG.128 gather (irreducible)
        }
        rec4[id] = make_float4(c4.x, c4.y, c4.z, w);
        fbA[id] = ia * FN;
    }
    __syncwarp();

    // ---------- main: 8-lane group g = vertex vbase+g, 4 features/lane ----------
    const int g = lane >> 3;
    const int sub = lane & 7;
    const float4* rp  = rec4 + g * KN;
    const int*    fbp = fbA  + g * KN;
    const float*  fbase = feats + sub * 4;

    unsigned long long P[4][5];
    #pragma unroll
    for (int c = 0; c < 4; ++c)
        #pragma unroll
        for (int j = 0; j < 5; ++j) P[c][j] = 0ull;

    #pragma unroll 8
    for (int k = 0; k < KN; ++k) {
        const float4 r = rp[k];                      // LDS.128, per-phase broadcast
        const int fb = fbp[k];                       // LDS.32 broadcast
        const float4 f4 = *(const float4*)(fbase + fb); // LDG.128, 1 line per group

        const float w = r.w, x = r.x, y = r.y, z = r.z;
        const float wx = w * x, wy = w * y, wz = w * z;
        const unsigned long long M0 = pack2(w,       wx);
        const unsigned long long M1 = pack2(wy,      wz);
        const unsigned long long M2 = pack2(wx * x,  wx * y);
        const unsigned long long M3 = pack2(wx * z,  wy * y);
        const unsigned long long M4 = pack2(wy * z,  wz * z);

        const unsigned long long d0 = pack2(f4.x, f4.x);
        const unsigned long long d1 = pack2(f4.y, f4.y);
        const unsigned long long d2 = pack2(f4.z, f4.z);
        const unsigned long long d3 = pack2(f4.w, f4.w);

        P[0][0] = ffma2(d0, M0, P[0][0]);
        P[0][1] = ffma2(d0, M1, P[0][1]);
        P[0][2] = ffma2(d0, M2, P[0][2]);
        P[0][3] = ffma2(d0, M3, P[0][3]);
        P[0][4] = ffma2(d0, M4, P[0][4]);

        P[1][0] = ffma2(d1, M0, P[1][0]);
        P[1][1] = ffma2(d1, M1, P[1][1]);
        P[1][2] = ffma2(d1, M2, P[1][2]);
        P[1][3] = ffma2(d1, M3, P[1][3]);
        P[1][4] = ffma2(d1, M4, P[1][4]);

        P[2][0] = ffma2(d2, M0, P[2][0]);
        P[2][1] = ffma2(d2, M1, P[2][1]);
        P[2][2] = ffma2(d2, M2, P[2][2]);
        P[2][3] = ffma2(d2, M3, P[2][3]);
        P[2][4] = ffma2(d2, M4, P[2][4]);

        P[3][0] = ffma2(d3, M0, P[3][0]);
        P[3][1] = ffma2(d3, M1, P[3][1]);
        P[3][2] = ffma2(d3, M2, P[3][2]);
        P[3][3] = ffma2(d3, M3, P[3][3]);
        P[3][4] = ffma2(d3, M4, P[3][4]);
    }

    // ---------- normalize + center into per-lane contiguous blocks ----------
    float cv[36];   // features 4*sub..4*sub+3 : 36 contiguous output floats
    float mn[12];
    #pragma unroll
    for (int c = 0; c < 4; ++c) {
        float S0, S1, S2, S3, S4, S5, S6, S7, S8, S9;
        unpack2(P[c][0], S0, S1);
        unpack2(P[c][1], S2, S3);
        unpack2(P[c][2], S4, S5);
        unpack2(P[c][3], S6, S7);
        unpack2(P[c][4], S8, S9);

        const float inv = __fdividef(1.0f, S0 + 1e-3f);
        const float mx = S1 * inv, my = S2 * inv, mz = S3 * inv;
        cv[c*9+0] = fmaf(-mx, mx, S4 * inv);
        cv[c*9+1] = fmaf(-mx, my, S5 * inv);
        cv[c*9+2] = fmaf(-mx, mz, S6 * inv);
        cv[c*9+4] = fmaf(-my, my, S7 * inv);
        cv[c*9+5] = fmaf(-my, mz, S8 * inv);
        cv[c*9+8] = fmaf(-mz, mz, S9 * inv);
        cv[c*9+3] = cv[c*9+1];
        cv[c*9+6] = cv[c*9+2];
        cv[c*9+7] = cv[c*9+5];
        mn[c*3+0] = mx; mn[c*3+1] = my; mn[c*3+2] = mz;
    }

    // ---------- two staging rounds: vertices {0,1} then {2,3} ----------
    #pragma unroll
    for (int round = 0; round < 2; ++round) {
        __syncwarp();
        if ((g >> 1) == round) {
            float* st = ws + (g & 1) * SSTR;
            float4* stc = (float4*)(st + 36 * sub);       // 16B aligned
            #pragma unroll
            for (int q = 0; q < 9; ++q)
                stc[q] = *(const float4*)(cv + 4 * q);
            float4* stm = (float4*)(st + 288 + 12 * sub);
            #pragma unroll
            for (int q = 0; q < 3; ++q)
                stm[q] = *(const float4*)(mn + 4 * q);
        }
        __syncwarp();
        // warp-wide coalesced copy of 768 floats (2 vertices)
        float* outp = out + (size_t)(vbase + 2 * round) * 384;
        #pragma unroll
        for (int r = 0; r < 6; ++r) {
            const int e = r * 128 + lane * 4;
            const int gv = (e >= 384) ? 1 : 0;
            if (vbase + 2 * round + gv < V) {
                float4 val = *(const float4*)(ws + gv * SSTR + (e - gv * 384));
                *(float4*)(outp + e) = val;
            }
        }
    }
}

extern "C" void kernel_launch(void* const* d_in, const int* in_sizes, int n_in,
                              void* d_out, int out_size) {
    const float* coords = (const float*)d_in[0];   // V x 3
    const float* distsq = (const float*)d_in[1];   // V x 40
    const float* feats  = (const float*)d_in[2];   // V x 32
    const int*   nidx   = (const int*)d_in[3];     // V x 40
    float* out = (float*)d_out;                    // V x 384
    const int V = in_sizes[0] / 3;

    pad_coords_kernel<<<(V + 255) / 256, 256>>>(coords, V);

    const int vpb = VPW * WPB;                     // 32 vertices per block
    nbcov_kernel<<<(V + vpb - 1) / vpb, WPB * 32>>>(distsq, feats, nidx, out, V);
}

// round 7
// speedup vs baseline: 1.1593x; 1.1593x over previous
#include <cuda_runtime.h>

#define KN 40
#define FN 32
#define VPW 4                 // vertices per warp
#define WPB 4                 // warps per block
#define ASTR 41               // float4 stride per vertex within each record array (stagger)
#define AN (VPW*ASTR)         // 164 float4 per array per warp
#define WSH (3*AN*4)          // floats per warp = 1968
#define SSTR 392              // epilogue staging stride (floats, float4 aligned)

__device__ float4 g_coords4[131072];   // padded coords scratch (V <= 131072)

__device__ __forceinline__ unsigned long long pack2(float lo, float hi) {
    unsigned long long r;
    asm("mov.b64 %0, {%1,%2};" : "=l"(r) : "f"(lo), "f"(hi));
    return r;
}
__device__ __forceinline__ void unpack2(unsigned long long v, float& lo, float& hi) {
    asm("mov.b64 {%0,%1}, %2;" : "=f"(lo), "=f"(hi) : "l"(v));
}
__device__ __forceinline__ unsigned long long ffma2(unsigned long long a,
                                                    unsigned long long b,
                                                    unsigned long long c) {
    unsigned long long d;
    asm("fma.rn.f32x2 %0, %1, %2, %3;" : "=l"(d) : "l"(a), "l"(b), "l"(c));
    return d;
}

__global__ void pad_coords_kernel(const float* __restrict__ c, int V) {
    int i = blockIdx.x * blockDim.x + threadIdx.x;
    if (i < V) {
        g_coords4[i] = make_float4(c[3*i], c[3*i+1], c[3*i+2], 0.f);
    }
}

__global__ __launch_bounds__(WPB * 32)
void nbcov_kernel(const float* __restrict__ distsq,
                  const float* __restrict__ feats,
                  const int* __restrict__ nidx,
                  float* __restrict__ out, int V)
{
    __shared__ float smem[WPB * WSH];
    const int warp = threadIdx.x >> 5;
    const int lane = threadIdx.x & 31;
    const int vbase = (blockIdx.x * WPB + warp) * VPW;
    float* ws = smem + warp * WSH;

    float4* A4 = (float4*)ws;            // [vloc*41 + k] : (w,  wx,  wy,  wz)
    float4* B4 = A4 + AN;                // [vloc*41 + k] : (wxx,wxy, wxz, wyy)
    float4* C4 = B4 + AN;                // [vloc*41 + k] : (wyz,wzz, fb,  0)

    // ---------- prep: 160 (vertex,k) tasks; precompute full moment records ----------
    #pragma unroll
    for (int t = 0; t < 5; ++t) {
        const int id = t * 32 + lane;          // 0..159, lexicographic (vloc,k)
        const int vloc = id / KN;
        const int k = id - vloc * KN;
        const int v = vbase + vloc;
        float w = 0.f;
        int ia = 0;
        float4 c4 = make_float4(0.f, 0.f, 0.f, 0.f);
        if (v < V) {
            const int ko = vbase * KN + id;    // contiguous loads
            int t_ia = nidx[ko];
            float d = distsq[ko];
            if (t_ia >= 0) { w = __expf(-10.0f * d); ia = t_ia; }
            c4 = g_coords4[ia];                // single LDG.128 gather (irreducible)
        }
        const float wx = w * c4.x, wy = w * c4.y, wz = w * c4.z;
        const int ridx = vloc * ASTR + k;
        A4[ridx] = make_float4(w, wx, wy, wz);
        B4[ridx] = make_float4(wx * c4.x, wx * c4.y, wx * c4.z, wy * c4.y);
        C4[ridx] = make_float4(wy * c4.z, wz * c4.z, __int_as_float(ia * FN), 0.f);
    }
    __syncwarp();

    // ---------- main: 8-lane group g = vertex vbase+g, 4 features/lane ----------
    const int g = lane >> 3;
    const int sub = lane & 7;
    const ulonglong2* ap = (const ulonglong2*)(A4 + g * ASTR);
    const ulonglong2* bp = (const ulonglong2*)(B4 + g * ASTR);
    const ulonglong2* cp = (const ulonglong2*)(C4 + g * ASTR);
    const float* fbase = feats + sub * 4;

    unsigned long long P[4][5];
    #pragma unroll
    for (int c = 0; c < 4; ++c)
        #pragma unroll
        for (int j = 0; j < 5; ++j) P[c][j] = 0ull;

    #pragma unroll 8
    for (int k = 0; k < KN; ++k) {
        const ulonglong2 Aq = ap[k];     // (w,wx) | (wy,wz)       broadcast LDS.128
        const ulonglong2 Bq = bp[k];     // (wxx,wxy) | (wxz,wyy)  broadcast LDS.128
        const ulonglong2 Cq = cp[k];     // (wyz,wzz) | (fb,pad)   broadcast LDS.128
        const int fb = (int)Cq.y;        // low 32 bits = ia*FN
        const float4 f4 = *(const float4*)(fbase + fb);   // LDG.128, 1 line per group

        const unsigned long long d0 = pack2(f4.x, f4.x);
        const unsigned long long d1 = pack2(f4.y, f4.y);
        const unsigned long long d2 = pack2(f4.z, f4.z);
        const unsigned long long d3 = pack2(f4.w, f4.w);

        P[0][0] = ffma2(d0, Aq.x, P[0][0]);
        P[0][1] = ffma2(d0, Aq.y, P[0][1]);
        P[0][2] = ffma2(d0, Bq.x, P[0][2]);
        P[0][3] = ffma2(d0, Bq.y, P[0][3]);
        P[0][4] = ffma2(d0, Cq.x, P[0][4]);

        P[1][0] = ffma2(d1, Aq.x, P[1][0]);
        P[1][1] = ffma2(d1, Aq.y, P[1][1]);
        P[1][2] = ffma2(d1, Bq.x, P[1][2]);
        P[1][3] = ffma2(d1, Bq.y, P[1][3]);
        P[1][4] = ffma2(d1, Cq.x, P[1][4]);

        P[2][0] = ffma2(d2, Aq.x, P[2][0]);
        P[2][1] = ffma2(d2, Aq.y, P[2][1]);
        P[2][2] = ffma2(d2, Bq.x, P[2][2]);
        P[2][3] = ffma2(d2, Bq.y, P[2][3]);
        P[2][4] = ffma2(d2, Cq.x, P[2][4]);

        P[3][0] = ffma2(d3, Aq.x, P[3][0]);
        P[3][1] = ffma2(d3, Aq.y, P[3][1]);
        P[3][2] = ffma2(d3, Bq.x, P[3][2]);
        P[3][3] = ffma2(d3, Bq.y, P[3][3]);
        P[3][4] = ffma2(d3, Cq.x, P[3][4]);
    }

    // ---------- normalize + center into per-lane contiguous blocks ----------
    float cv[36];   // features 4*sub..4*sub+3 : 36 contiguous output floats
    float mn[12];
    #pragma unroll
    for (int c = 0; c < 4; ++c) {
        float S0, S1, S2, S3, S4, S5, S6, S7, S8, S9;
        unpack2(P[c][0], S0, S1);
        unpack2(P[c][1], S2, S3);
        unpack2(P[c][2], S4, S5);
        unpack2(P[c][3], S6, S7);
        unpack2(P[c][4], S8, S9);

        const float inv = __fdividef(1.0f, S0 + 1e-3f);
        const float mx = S1 * inv, my = S2 * inv, mz = S3 * inv;
        cv[c*9+0] = fmaf(-mx, mx, S4 * inv);
        cv[c*9+1] = fmaf(-mx, my, S5 * inv);
        cv[c*9+2] = fmaf(-mx, mz, S6 * inv);
        cv[c*9+4] = fmaf(-my, my, S7 * inv);
        cv[c*9+5] = fmaf(-my, mz, S8 * inv);
        cv[c*9+8] = fmaf(-mz, mz, S9 * inv);
        cv[c*9+3] = cv[c*9+1];
        cv[c*9+6] = cv[c*9+2];
        cv[c*9+7] = cv[c*9+5];
        mn[c*3+0] = mx; mn[c*3+1] = my; mn[c*3+2] = mz;
    }

    // ---------- two staging rounds: vertices {0,1} then {2,3} ----------
    #pragma unroll
    for (int round = 0; round < 2; ++round) {
        __syncwarp();
        if ((g >> 1) == round) {
            float* st = ws + (g & 1) * SSTR;
            float4* stc = (float4*)(st + 36 * sub);       // 16B aligned
            #pragma unroll
            for (int q = 0; q < 9; ++q)
                stc[q] = *(const float4*)(cv + 4 * q);
            float4* stm = (float4*)(st + 288 + 12 * sub);
            #pragma unroll
            for (int q = 0; q < 3; ++q)
                stm[q] = *(const float4*)(mn + 4 * q);
        }
        __syncwarp();
        // warp-wide coalesced copy of 768 floats (2 vertices)
        float* outp = out + (size_t)(vbase + 2 * round) * 384;
        #pragma unroll
        for (int r = 0; r < 6; ++r) {
            const int e = r * 128 + lane * 4;
            const int gv = (e >= 384) ? 1 : 0;
            if (vbase + 2 * round + gv < V) {
                float4 val = *(const float4*)(ws + gv * SSTR + (e - gv * 384));
                *(float4*)(outp + e) = val;
            }
        }
    }
}

extern "C" void kernel_launch(void* const* d_in, const int* in_sizes, int n_in,
                              void* d_out, int out_size) {
    const float* coords = (const float*)d_in[0];   // V x 3
    const float* distsq = (const float*)d_in[1];   // V x 40
    const float* feats  = (const float*)d_in[2];   // V x 32
    const int*   nidx   = (const int*)d_in[3];     // V x 40
    float* out = (float*)d_out;                    // V x 384
    const int V = in_sizes[0] / 3;

    pad_coords_kernel<<<(V + 255) / 256, 256>>>(coords, V);

    const int vpb = VPW * WPB;                     // 16 vertices per block
    nbcov_kernel<<<(V + vpb - 1) / vpb, WPB * 32>>>(distsq, feats, nidx, out, V);
}